// round 17
// baseline (speedup 1.0000x reference)
#include <cuda_runtime.h>
#include <cuda_bf16.h>
#include <cstdint>

// ============================================================================
// EinetMixture: route each row to nearest centroid (E=8), then compute only
// that expert's Gaussian-leaf log-likelihood (K=64 leaves) + logsumexp.
//
// leaf_ll[b,k] = sum_d ( a[e,k,d]*x^2 + b[e,k,d]*x ) + c[e,k]
// d-reduction = bf16 mma.sync GEMM; K-dim interleaved as (x[d], x^2[d]) pairs
// matching W pairs (bcoef, acoef). A staged in smem as RAW f32 x (cp.async,
// 256B/row/chunk for DRAM burst locality); pack at fragment-load time.
//
// TWO launches: k01 (route blocks || prep blocks) -> k4.
// ccomb finalized per-CTA inside k4 from per-chunk csum partials.
// d_cursor re-zeroed by k4's last block (self-resetting ticket counter).
// ============================================================================

#define B_N 32768
#define D_N 784
#define D_PAD 832             // 13 chunks of 64 d (pad coeffs are zero)
#define E_N 8
#define K_N 64
#define F4_PER_ROW 196        // 784/4
#define X_ROW_BYTES 3136      // 784*4

#define TILE_M 128
#define CHUNK_D 64            // d's per K4 chunk (128 bf16 of K)
#define NCHUNK 13
#define KSTEPS 8              // k16 steps per chunk
#define NSTAGE 2
#define A_PITCH 68            // f32 pitch; frag banks (4g+tig) distinct
#define B_PITCH 72            // u32 pitch; frag banks (8tig+g) distinct
#define C_PITCH 66            // float pitch for epilogue

#define ROUTE_BLOCKS 512      // B_N / 64
#define PREP_BLOCKS  (E_N * NCHUNK)   // 104

#define A_BUF_BYTES (TILE_M * A_PITCH * 4)        // 34816
#define B_BUF_BYTES (CHUNK_D * B_PITCH * 4)       // 18432
#define SM_B_OFF   (NSTAGE * A_BUF_BYTES)         // 69632
#define SM_IDX_OFF (SM_B_OFF + NSTAGE * B_BUF_BYTES)  // 106496
#define SM_CC_OFF  (SM_IDX_OFF + TILE_M * 4)      // 107008
#define SM_LG_OFF  (SM_CC_OFF + K_N * 4)          // 107264
#define SM_TOTAL_K4 (SM_LG_OFF + K_N * 4)         // 107520 (x2 CTAs = 215KB)

#define LOG_2PI 1.8378770664093453f

// ---------------- device scratch (no allocation allowed) ----------------
__device__ __align__(16) uint32_t d_Wpack[E_N * D_PAD * K_N]; // [e][d][k] bf16x2 (b,a)
__device__ float    d_csumPart[E_N * NCHUNK * K_N];  // per-chunk csum partials
__device__ int      d_cursor[E_N];              // per-expert cursor == final counts
__device__ int      d_expertList[E_N * B_N];    // row indices grouped by expert
__device__ int      d_done = 0;                 // k4 completion ticket (self-reset)

// ---------------- helpers ----------------
__device__ __forceinline__ uint32_t pack_x_x2(float v) {
    __nv_bfloat162 p = __floats2bfloat162_rn(v, v * v);   // lo = x, hi = x^2
    return *reinterpret_cast<uint32_t*>(&p);
}

__device__ __forceinline__ void mma_bf16(float* c, const uint32_t* a,
                                         uint32_t b0, uint32_t b1) {
    asm volatile(
        "mma.sync.aligned.m16n8k16.row.col.f32.bf16.bf16.f32 "
        "{%0,%1,%2,%3}, {%4,%5,%6,%7}, {%8,%9}, {%0,%1,%2,%3};\n"
        : "+f"(c[0]), "+f"(c[1]), "+f"(c[2]), "+f"(c[3])
        : "r"(a[0]), "r"(a[1]), "r"(a[2]), "r"(a[3]), "r"(b0), "r"(b1));
}

__device__ __forceinline__ void cp_async16(uint32_t smem_addr, const void* gptr) {
    asm volatile("cp.async.cg.shared.global [%0], [%1], 16;\n"
                 :: "r"(smem_addr), "l"(gptr));
}
#define CP_COMMIT() asm volatile("cp.async.commit_group;\n" ::: "memory")
#define CP_WAIT0()  asm volatile("cp.async.wait_group 0;\n" ::: "memory")

// ============================================================================
// K01: merged prep + route. 256 threads.
//   blocks [0, 512): routing + scatter (one warp per 8 rows).
//   blocks [512, 616): weight prep, one (expert, 64-d chunk) per block,
//     smem-transposed so d_Wpack writes are fully coalesced (16KB contiguous).
// ============================================================================
#define RPW 8
__global__ void __launch_bounds__(256) k01_prep_route(
        const float* __restrict__ x,
        const float* __restrict__ centroids,
        const float* __restrict__ means,
        const float* __restrict__ log_stds) {
    int tid = threadIdx.x;

    if (blockIdx.x >= ROUTE_BLOCKS) {
        // ---------------- PREP block: (e, chunk cb) -> [64 d][64 k] tile ----
        __shared__ uint32_t tile[CHUNK_D * K_N];   // 16KB
        __shared__ float red4[256];                // red4[k*4 + seg]
        int pb = blockIdx.x - ROUTE_BLOCKS;
        int e  = pb / NCHUNK;
        int cb = pb - e * NCHUNK;

        int k   = tid >> 2;          // 0..63
        int seg = tid & 3;           // 16-d sub-block
        int d0  = cb * CHUNK_D + seg * 16;

        const float* mrow = means    + (size_t)(e * K_N + k) * D_N + d0;
        const float* lrow = log_stds + (size_t)(e * K_N + k) * D_N + d0;

        bool valid = d0 < D_N;       // whole 16-d block valid (784 = 49*16)
        float mv[16], lv[16];
#pragma unroll
        for (int q = 0; q < 4; q++) {
            float4 m4, l4;
            if (valid) {
                m4 = *reinterpret_cast<const float4*>(mrow + q * 4);
                l4 = *reinterpret_cast<const float4*>(lrow + q * 4);
            } else {
                m4 = l4 = make_float4(0.f, 0.f, 0.f, 0.f);
            }
            mv[q*4]=m4.x; mv[q*4+1]=m4.y; mv[q*4+2]=m4.z; mv[q*4+3]=m4.w;
            lv[q*4]=l4.x; lv[q*4+1]=l4.y; lv[q*4+2]=l4.z; lv[q*4+3]=l4.w;
        }

        float csum = 0.f;
#pragma unroll
        for (int j = 0; j < 16; j++) {
            uint32_t pk = 0;
            if (valid) {
                float iv = __expf(-2.f * lv[j]);
                float bc = mv[j] * iv;
                csum += -0.5f * mv[j] * mv[j] * iv - lv[j];
                __nv_bfloat162 p = __floats2bfloat162_rn(bc, -0.5f * iv); // lo=b, hi=a
                pk = *reinterpret_cast<uint32_t*>(&p);
            }
            tile[(seg * 16 + j) * K_N + k] = pk;
        }
        red4[k * 4 + seg] = csum;
        __syncthreads();

        // coalesced 16KB write: thread -> 4 x uint4 at contiguous offsets
        size_t baseW = ((size_t)(e * D_PAD + cb * CHUNK_D)) << 6;
        uint4* dst = reinterpret_cast<uint4*>(d_Wpack + baseW);
        const uint4* src = reinterpret_cast<const uint4*>(tile);
#pragma unroll
        for (int i = 0; i < 4; i++)
            dst[tid + i * 256] = src[tid + i * 256];

        if (tid < K_N) {
            float s = red4[tid * 4] + red4[tid * 4 + 1]
                    + red4[tid * 4 + 2] + red4[tid * 4 + 3];
            d_csumPart[(e * NCHUNK + cb) * K_N + tid] = s;
        }
        return;
    }

    // ---------------- ROUTE block ----------------
    __shared__ float4 cent[E_N * F4_PER_ROW];   // 25088 B
    __shared__ float  cnormS[E_N];
    __shared__ int hist[E_N];
    __shared__ int base[E_N];
    int warp = tid >> 5, lane = tid & 31;
    if (tid < E_N) hist[tid] = 0;
    const float4* c4 = reinterpret_cast<const float4*>(centroids);
    for (int j = tid; j < E_N * F4_PER_ROW; j += 256) cent[j] = c4[j];
    __syncthreads();

    // centroid norms: warp w handles expert w
    {
        float cn = 0.f;
        for (int j = lane; j < F4_PER_ROW; j += 32) {
            float4 cv = cent[warp * F4_PER_ROW + j];
            cn += cv.x * cv.x + cv.y * cv.y + cv.z * cv.z + cv.w * cv.w;
        }
#pragma unroll
        for (int o = 16; o; o >>= 1) cn += __shfl_xor_sync(0xffffffffu, cn, o);
        if (lane == 0) cnormS[warp] = cn;
    }
    __syncthreads();

    int b0 = blockIdx.x * (8 * RPW) + warp * RPW;
    const float4* x4 = reinterpret_cast<const float4*>(x) + (size_t)b0 * F4_PER_ROW;

    float dot[RPW][E_N];
#pragma unroll
    for (int r = 0; r < RPW; r++)
#pragma unroll
        for (int e = 0; e < E_N; e++) dot[r][e] = 0.f;

    for (int j = lane; j < F4_PER_ROW; j += 32) {
        float4 xv[RPW];
#pragma unroll
        for (int r = 0; r < RPW; r++) xv[r] = x4[(size_t)r * F4_PER_ROW + j];
#pragma unroll
        for (int e = 0; e < E_N; e++) {
            float4 cv = cent[e * F4_PER_ROW + j];
#pragma unroll
            for (int r = 0; r < RPW; r++)
                dot[r][e] += xv[r].x * cv.x + xv[r].y * cv.y
                           + xv[r].z * cv.z + xv[r].w * cv.w;
        }
    }
#pragma unroll
    for (int r = 0; r < RPW; r++)
#pragma unroll
        for (int e = 0; e < E_N; e++)
#pragma unroll
            for (int o = 16; o; o >>= 1)
                dot[r][e] += __shfl_xor_sync(0xffffffffu, dot[r][e], o);

    int bi[RPW], rk[RPW];
    if (lane == 0) {
#pragma unroll
        for (int r = 0; r < RPW; r++) {
            float best = 3.4e38f;
            int sel = 0;
#pragma unroll
            for (int e = 0; e < E_N; e++) {
                float s = cnormS[e] - 2.f * dot[r][e];
                if (s < best) { best = s; sel = e; }   // first-min == argmin
            }
            bi[r] = sel;
            rk[r] = atomicAdd(&hist[sel], 1);          // block-local rank
        }
    }
    __syncthreads();
    if (tid < E_N)
        base[tid] = hist[tid] ? atomicAdd(&d_cursor[tid], hist[tid]) : 0;
    __syncthreads();
    if (lane == 0) {
#pragma unroll
        for (int r = 0; r < RPW; r++)
            d_expertList[bi[r] * B_N + base[bi[r]] + rk[r]] = b0 + r;
    }
}

// ============================================================================
// K4: grouped GEMM, 512 threads (16 warps), warp tile 16x32 (8m x 2n),
// 13 chunks of 64 d (256B/row DRAM bursts), 2-stage cp.async pipeline
// (one-chunk lookahead ~ a full chunk of MMA time), one sync/chunk.
// A staged as RAW f32 x; pack (x,x^2)->bf16x2 at fragment-load.
// Hazard: writing buf (cb+1)&1 races only MMA_{cb-1} (same buffer),
// finished before sync_cb in every warp's program order.
// ============================================================================
__global__ void __launch_bounds__(512, 2) k4_gemm(const float* __restrict__ x,
                                                  const float* __restrict__ logits,
                                                  float* __restrict__ out) {
    extern __shared__ __align__(16) unsigned char raw[];
    int*   rowIdxS = reinterpret_cast<int*>(raw + SM_IDX_OFF);
    float* ccombS  = reinterpret_cast<float*>(raw + SM_CC_OFF);
    float* lgS     = reinterpret_cast<float*>(raw + SM_LG_OFF);
    float* Cs      = reinterpret_cast<float*>(raw);   // epilogue, aliases A bufs

    int tid = threadIdx.x;
    int t = blockIdx.x;

    // find (expert, tile) from d_cursor (== per-expert counts after K01)
    int e = -1, tileIn = 0, nrows = 0;
    {
        int ts = 0;
#pragma unroll
        for (int i = 0; i < E_N; i++) {
            int c = d_cursor[i];
            int tiles = (c + TILE_M - 1) >> 7;
            if (e < 0 && t >= ts && t < ts + tiles) {
                e = i; tileIn = t - ts;
                nrows = min(TILE_M, c - tileIn * TILE_M);
            }
            ts += tiles;
        }
    }
    if (e < 0) {   // beyond last tile: still participate in the ticket
        if (tid == 0) {
            __threadfence();
            if (atomicAdd(&d_done, 1) == gridDim.x - 1) {
#pragma unroll
                for (int i = 0; i < E_N; i++) d_cursor[i] = 0;
                __threadfence();
                d_done = 0;
            }
        }
        return;
    }

    // ---- prologue: row indices + ccomb reconstruction ----
    if (tid < TILE_M)
        rowIdxS[tid] = d_expertList[e * B_N + tileIn * TILE_M
                                    + ((tid < nrows) ? tid : 0)];
    float csk = 0.f;
    if (tid < K_N) {
        lgS[tid] = logits[e * K_N + tid];
        const float* p = d_csumPart + (size_t)e * (NCHUNK * K_N) + tid;
#pragma unroll
        for (int c = 0; c < NCHUNK; c++) csk += p[c * K_N];
    }
    __syncthreads();
    if (tid < K_N) {
        float mx = lgS[0];
#pragma unroll 8
        for (int j = 1; j < K_N; j++) mx = fmaxf(mx, lgS[j]);
        float s = 0.f;
#pragma unroll 8
        for (int j = 0; j < K_N; j++) s += __expf(lgS[j] - mx);
        float lse = mx + logf(s);
        ccombS[tid] = csk - 0.5f * (float)D_N * LOG_2PI + lgS[tid] - lse;
    }
    __syncthreads();

    const uint32_t* WbE = d_Wpack + (size_t)e * (D_PAD * K_N);
    uint32_t smem_u32 = (uint32_t)__cvta_generic_to_shared(raw);

    int warp = tid >> 5, lane = tid & 31;
    int g = lane >> 2, tig = lane & 3;
    int mw = warp >> 1, nw = warp & 1;
    int mrow0 = mw * 16, n0 = nw * 32;

    float acc[4][4];
#pragma unroll
    for (int n = 0; n < 4; n++)
#pragma unroll
        for (int q = 0; q < 4; q++) acc[n][q] = 0.f;

    // A producer mapping: 4 threads per row, 4 x 16B each (256 B/row/chunk)
    int arow = tid >> 2, aseg = tid & 3;
    const char* xrowA = reinterpret_cast<const char*>(x)
                      + (size_t)rowIdxS[arow] * X_ROW_BYTES;

    auto issueA = [&](int cb, int buf) {
        uint32_t adst = smem_u32 + buf * A_BUF_BYTES + arow * (A_PITCH * 4);
        int base = cb * 256;
#pragma unroll
        for (int p = 0; p < 4; p++) {
            int off = aseg * 64 + p * 16;
            if (base + off < X_ROW_BYTES)                 // only clips on cb=12
                cp_async16(adst + off, xrowA + base + off);
        }
    };
    auto issueB = [&](int cb, int buf) {
        uint32_t bdst = smem_u32 + SM_B_OFF + buf * B_BUF_BYTES;
        int kk = tid >> 3, n4 = (tid & 7) * 4;            // 64 rows, 8 thr/row
        const uint32_t* src = WbE + (size_t)cb * (CHUNK_D * K_N) + kk * K_N + n4;
        cp_async16(bdst + (kk * B_PITCH + n4) * 4,        src);
        cp_async16(bdst + (kk * B_PITCH + n4 + 32) * 4,   src + 32);
    };

    // ---- prologue: chunk 0 ----
    issueA(0, 0); issueB(0, 0); CP_COMMIT();

    int buf = 0;
    for (int cb = 0; cb < NCHUNK; cb++) {
        const float*    Af = reinterpret_cast<const float*>(raw + buf * A_BUF_BYTES);
        const uint32_t* Bs = reinterpret_cast<const uint32_t*>(raw + SM_B_OFF + buf * B_BUF_BYTES);

        CP_WAIT0();          // chunk cb landed (issued a full MMA-block ago)
        __syncthreads();     // visible; MMA_{cb-1} finished everywhere

        if (cb + 1 < NCHUNK) {
            issueA(cb + 1, buf ^ 1);   // safe: MMA_{cb-1} done by this sync
            issueB(cb + 1, buf ^ 1);
            CP_COMMIT();
        }

        // ---- MMA: 16 rows x 32 cols, 8 k16 steps; pack A frags on the fly ----
#pragma unroll
        for (int ks = 0; ks < KSTEPS; ks++) {
            int kkb = ks * 8;
            uint32_t a[4];
            a[0] = pack_x_x2(Af[(mrow0 + g)     * A_PITCH + kkb + tig]);
            a[1] = pack_x_x2(Af[(mrow0 + 8 + g) * A_PITCH + kkb + tig]);
            a[2] = pack_x_x2(Af[(mrow0 + g)     * A_PITCH + kkb + tig + 4]);
            a[3] = pack_x_x2(Af[(mrow0 + 8 + g) * A_PITCH + kkb + tig + 4]);
#pragma unroll
            for (int nt = 0; nt < 4; nt++) {
                uint32_t b0 = Bs[(kkb + tig)     * B_PITCH + n0 + nt * 8 + g];
                uint32_t b1 = Bs[(kkb + tig + 4) * B_PITCH + n0 + nt * 8 + g];
                mma_bf16(acc[nt], a, b0, b1);
            }
        }
        buf ^= 1;
    }
    __syncthreads();   // all MMAs done before Cs aliases the A buffers

    // ---- epilogue: accums -> smem ----
    {
        int row0 = mrow0 + g;
#pragma unroll
        for (int nt = 0; nt < 4; nt++) {
            int col = n0 + nt * 8 + tig * 2;
            Cs[row0 * C_PITCH + col]           = acc[nt][0];
            Cs[row0 * C_PITCH + col + 1]       = acc[nt][1];
            Cs[(row0 + 8) * C_PITCH + col]     = acc[nt][2];
            Cs[(row0 + 8) * C_PITCH + col + 1] = acc[nt][3];
        }
    }
    __syncthreads();

    // ---- logsumexp per row, scatter to original index ----
    if (tid < TILE_M) {
        const float* crow = &Cs[tid * C_PITCH];
        float mx = -3.4e38f;
#pragma unroll 8
        for (int j = 0; j < K_N; j++) mx = fmaxf(mx, crow[j] + ccombS[j]);
        float s = 0.f;
#pragma unroll 8
        for (int j = 0; j < K_N; j++) s += expf(crow[j] + ccombS[j] - mx);
        float ll = mx + logf(s);
        if (tid < nrows) out[rowIdxS[tid]] = ll;
    }

    // ---- completion ticket: last block resets cursors for next replay ----
    if (tid == 0) {
        __threadfence();
        if (atomicAdd(&d_done, 1) == gridDim.x - 1) {
#pragma unroll
            for (int i = 0; i < E_N; i++) d_cursor[i] = 0;
            __threadfence();
            d_done = 0;
        }
    }
}

// ============================================================================
extern "C" void kernel_launch(void* const* d_in, const int* in_sizes, int n_in,
                              void* d_out, int out_size) {
    const float* x         = (const float*)d_in[0];
    const float* centroids = (const float*)d_in[1];
    const float* means     = (const float*)d_in[2];
    const float* log_stds  = (const float*)d_in[3];
    const float* logits    = (const float*)d_in[4];
    float* out = (float*)d_out;

    static bool attr_set = false;
    if (!attr_set) {
        cudaFuncSetAttribute(k4_gemm, cudaFuncAttributeMaxDynamicSharedMemorySize,
                             SM_TOTAL_K4);
        attr_set = true;
    }

    k01_prep_route<<<ROUTE_BLOCKS + PREP_BLOCKS, 256>>>(x, centroids, means, log_stds);
    k4_gemm<<<B_N / TILE_M + E_N, 512, SM_TOTAL_K4>>>(x, logits, out);
}